// round 5
// baseline (speedup 1.0000x reference)
#include <cuda_runtime.h>
#include <cuda_bf16.h>

#define NEGV (-1e30f)

// ---------------- scratch (no allocations allowed) ----------------
__device__ float g_pooled[256 * 2048];
__device__ float g_part1[8 * 256 * 200];   // FC1 split-K partials

__device__ __forceinline__ float2 fmax2(float2 a, float2 b) {
    return make_float2(fmaxf(a.x, b.x), fmaxf(a.y, b.y));
}

// packed f32x2 helpers (FFMA2 path — only reachable via PTX)
__device__ __forceinline__ unsigned long long dup2(float b) {
    unsigned long long r;
    asm("mov.b64 %0, {%1, %1};" : "=l"(r) : "f"(b));
    return r;
}
__device__ __forceinline__ void ffma2(unsigned long long& acc,
                                      unsigned long long a,
                                      unsigned long long b) {
    asm("fma.rn.f32x2 %0, %1, %2, %3;" : "=l"(acc) : "l"(a), "l"(b), "l"(acc));
}
__device__ __forceinline__ float2 unpack2(unsigned long long v) {
    float lo, hi;
    asm("mov.b64 {%0, %1}, %2;" : "=f"(lo), "=f"(hi) : "l"(v));
    return make_float2(lo, hi);
}

// ---------------- Kernel 1: ROI adaptive 2x2 max pool ----------------
// grid = 256 (one block per proposal), block = 256 threads (float2 channels)
__global__ void roipool_kernel(const float* __restrict__ fm,
                               const int* __restrict__ coords) {
    const int p = blockIdx.x;
    const int tid = threadIdx.x;

    const int y0 = coords[p * 4 + 0];
    const int x0 = coords[p * 4 + 1];
    const int y1 = coords[p * 4 + 2];
    const int x1 = coords[p * 4 + 3];

    const int sy = min(y0 / 8, 74);
    const int sx = min(x0 / 8, 126);
    const int ey = (y1 + 7) / 8;
    const int ex = (x1 + 7) / 8;
    const int h = max(ey - sy, 2);
    const int w = max(ex - sx, 2);

    const int e0r = (h + 1) / 2;   // bin0 rows: [0, e0r)
    const int s1r = h / 2;         // bin1 rows: [s1r, h)
    const int e0c = (w + 1) / 2;
    const int s1c = w / 2;
    const int rmax = min(h, 24);
    const int cmax = min(w, 24);
    const int climit = min(cmax, 128 - sx);   // columns with in-bounds gx

    float2 m00 = make_float2(NEGV, NEGV), m01 = m00, m10 = m00, m11 = m00;

    for (int r = 0; r < rmax; r++) {
        const int gy = sy + r;
        const bool rowv = (gy < 76);
        const float* rowbase = fm + ((size_t)(gy * 128 + sx)) * 512 + 2 * tid;

        float2 c0 = make_float2(NEGV, NEGV);
        float2 c1 = make_float2(NEGV, NEGV);

        #pragma unroll 8
        for (int c = 0; c < cmax; c++) {
            float2 v = make_float2(0.0f, 0.0f);
            if (rowv && c < climit) {
                v = *reinterpret_cast<const float2*>(rowbase + (size_t)c * 512);
            }
            if (c < e0c)  c0 = fmax2(c0, v);
            if (c >= s1c) c1 = fmax2(c1, v);
        }
        if (r < e0r)  { m00 = fmax2(m00, c0); m01 = fmax2(m01, c1); }
        if (r >= s1r) { m10 = fmax2(m10, c0); m11 = fmax2(m11, c1); }
    }

    float* outp = g_pooled + (size_t)p * 2048 + 2 * tid;
    *reinterpret_cast<float2*>(outp + 0 * 512) = m00;
    *reinterpret_cast<float2*>(outp + 1 * 512) = m01;
    *reinterpret_cast<float2*>(outp + 2 * 512) = m10;
    *reinterpret_cast<float2*>(outp + 3 * 512) = m11;
}

// ---------------- Kernel 2: FC1 split-K partial GEMM (FFMA2) ----------------
// A = pooled [256,2048], B = W1 [2048,200]
// grid = (32 mtiles of 8 rows, 8 K-splits of 256), block = 200 threads
// A staged TRANSPOSED in smem: As[k][r] so one LDS.128 = rows 0-3 (two f32x2 pairs)
__global__ void fc1_partial(const float* __restrict__ A,
                            const float* __restrict__ B,
                            float* __restrict__ part) {
    __shared__ float As[256][8];
    const int mt = blockIdx.x;
    const int ks = blockIdx.y;
    const int tid = threadIdx.x;
    const int m0 = mt * 8;
    const int k0 = ks * 256;

    for (int idx = tid; idx < 8 * 256; idx += 200) {
        const int r = idx >> 8;
        const int k = idx & 255;
        As[k][r] = A[(size_t)(m0 + r) * 2048 + k0 + k];
    }
    __syncthreads();

    const int j = tid;
    unsigned long long acc01 = 0ull, acc23 = 0ull, acc45 = 0ull, acc67 = 0ull;

    const float* Bp = B + (size_t)k0 * 200 + j;
    #pragma unroll 4
    for (int k = 0; k < 256; k++) {
        const unsigned long long bd = dup2(Bp[(size_t)k * 200]);
        const ulonglong2 lo = *reinterpret_cast<const ulonglong2*>(&As[k][0]);
        const ulonglong2 hi = *reinterpret_cast<const ulonglong2*>(&As[k][4]);
        ffma2(acc01, lo.x, bd);
        ffma2(acc23, lo.y, bd);
        ffma2(acc45, hi.x, bd);
        ffma2(acc67, hi.y, bd);
    }

    float* out = part + ((size_t)ks * 256 + m0) * 200 + j;
    const float2 r01 = unpack2(acc01);
    const float2 r23 = unpack2(acc23);
    const float2 r45 = unpack2(acc45);
    const float2 r67 = unpack2(acc67);
    out[0 * 200] = r01.x;  out[1 * 200] = r01.y;
    out[2 * 200] = r23.x;  out[3 * 200] = r23.y;
    out[4 * 200] = r45.x;  out[5 * 200] = r45.y;
    out[6 * 200] = r67.x;  out[7 * 200] = r67.y;
}

// ---------------- Kernel 3: fused reduce + FC2 + heads + decode ----------------
// grid = 128 blocks (2 proposals each), block = 200 threads
__global__ void fused_tail(const float* __restrict__ part,
                           const float* __restrict__ b1,
                           const float* __restrict__ W2,
                           const float* __restrict__ b2,
                           const int* __restrict__ coords,
                           const float* __restrict__ W3,
                           const float* __restrict__ b3,
                           const float* __restrict__ W4,
                           const float* __restrict__ b4,
                           float* __restrict__ out) {
    __shared__ float2 Ap[200];        // f1 row-pair, interleaved (row0, row1)
    __shared__ float fs[2][200];      // f2 rows
    __shared__ float op[2][21][4];    // head partial sums
    __shared__ float os[2][21];       // head outputs

    const int m0 = blockIdx.x * 2;
    const int tid = threadIdx.x;
    const int j = tid;

    // ---- phase 1: split-K reduce + bias + relu -> f1 pair in smem ----
    {
        const float bj = b1[j];
        float s0 = bj, s1 = bj;
        const float* p0 = part + (size_t)m0 * 200 + j;
        #pragma unroll
        for (int ks = 0; ks < 8; ks++) {
            s0 += p0[(size_t)ks * 51200];
            s1 += p0[(size_t)ks * 51200 + 200];
        }
        Ap[j] = make_float2(fmaxf(s0, 0.0f), fmaxf(s1, 0.0f));
    }
    __syncthreads();

    // ---- phase 2: FC2 (FFMA2 over row pair) + relu -> fs ----
    {
        unsigned long long acc = 0ull;
        const float* Bp = W2 + j;
        #pragma unroll 4
        for (int k = 0; k < 200; k++) {
            const unsigned long long bd = dup2(Bp[(size_t)k * 200]);
            const unsigned long long a =
                *reinterpret_cast<const unsigned long long*>(&Ap[k]);
            ffma2(acc, a, bd);
        }
        const float2 v = unpack2(acc);
        const float bj = b2[j];
        fs[0][j] = fmaxf(v.x + bj, 0.0f);
        fs[1][j] = fmaxf(v.y + bj, 0.0f);
    }
    __syncthreads();

    // ---- phase 3: head dot products, 4-way K-split over 168 threads ----
    if (tid < 168) {
        const int prop = tid / 84;
        const int rem = tid % 84;
        const int o = rem / 4;        // 0..20
        const int ks = rem % 4;       // 0..3
        const int kb = ks * 50;
        const float* wp = (o < 16) ? (W3 + o) : (W4 + (o - 16));
        const int stride = (o < 16) ? 16 : 5;
        float s0 = 0.f, s1 = 0.f;
        #pragma unroll 5
        for (int k = 0; k < 50; k += 2) {
            s0 = fmaf(fs[prop][kb + k],     wp[(size_t)(kb + k) * stride],     s0);
            s1 = fmaf(fs[prop][kb + k + 1], wp[(size_t)(kb + k + 1) * stride], s1);
        }
        op[prop][o][ks] = s0 + s1;
    }
    __syncthreads();

    if (tid < 42) {
        const int prop = tid / 21;
        const int o = tid % 21;
        const float bias = (o < 16) ? b3[o] : b4[o - 16];
        os[prop][o] = bias + (op[prop][o][0] + op[prop][o][1]) +
                             (op[prop][o][2] + op[prop][o][3]);
    }
    __syncthreads();

    // ---- phase 4: softmax / argmax / box decode for the 2 proposals ----
    if (tid < 2) {
        const int p = m0 + tid;
        const float l0 = os[tid][16], l1 = os[tid][17], l2 = os[tid][18],
                    l3 = os[tid][19], l4 = os[tid][20];
        int cls = 0;
        float best = l0;
        if (l1 > best) { best = l1; cls = 1; }
        if (l2 > best) { best = l2; cls = 2; }
        if (l3 > best) { best = l3; cls = 3; }
        if (l4 > best) { best = l4; cls = 4; }
        const float mx = best;
        const float e0 = expf(l0 - mx), e1 = expf(l1 - mx), e2 = expf(l2 - mx),
                    e3 = expf(l3 - mx), e4 = expf(l4 - mx);
        const float sum = e0 + e1 + e2 + e3 + e4;
        const float score = fmaxf(fmaxf(e1, e2), fmaxf(e3, e4)) / sum;

        const int jj = max(cls - 1, 0);
        const float r0 = os[tid][jj * 4 + 0];
        const float r1 = os[tid][jj * 4 + 1];
        const float r2 = os[tid][jj * 4 + 2];
        const float r3 = os[tid][jj * 4 + 3];

        const float y0 = (float)coords[p * 4 + 0];
        const float x0 = (float)coords[p * 4 + 1];
        const float y1 = (float)coords[p * 4 + 2];
        const float x1 = (float)coords[p * 4 + 3];
        const float ph = y1 - y0;
        const float pw = x1 - x0;
        const float py = y0 + 0.5f * ph;
        const float px = x0 + 0.5f * pw;

        out[p * 4 + 0] = fmaf(ph, r0, py);
        out[p * 4 + 1] = fmaf(pw, r1, px);
        out[p * 4 + 2] = ph * fminf(fmaxf(expf(r2), 0.001f), 20.0f);
        out[p * 4 + 3] = pw * fminf(fmaxf(expf(r3), 0.001f), 20.0f);
        out[1024 + p] = score;
        out[1280 + p] = (cls != 0) ? 1.0f : 0.0f;
    }
}

// ---------------- launch ----------------
extern "C" void kernel_launch(void* const* d_in, const int* in_sizes, int n_in,
                              void* d_out, int out_size) {
    const float* fm     = (const float*)d_in[0];
    const int*   coords = (const int*)d_in[1];
    const float* W1 = (const float*)d_in[2];
    const float* b1 = (const float*)d_in[3];
    const float* W2 = (const float*)d_in[4];
    const float* b2 = (const float*)d_in[5];
    const float* W3 = (const float*)d_in[6];
    const float* b3 = (const float*)d_in[7];
    const float* W4 = (const float*)d_in[8];
    const float* b4 = (const float*)d_in[9];
    float* out = (float*)d_out;

    float *pooled = nullptr, *part1 = nullptr;
    cudaGetSymbolAddress((void**)&pooled, g_pooled);
    cudaGetSymbolAddress((void**)&part1, g_part1);

    roipool_kernel<<<256, 256>>>(fm, coords);
    fc1_partial<<<dim3(32, 8), 200>>>(pooled, W1, part1);
    fused_tail<<<128, 200>>>(part1, b1, W2, b2, coords, W3, b3, W4, b4, out);
}

// round 6
// speedup vs baseline: 1.9638x; 1.9638x over previous
#include <cuda_runtime.h>
#include <cuda_bf16.h>

#define NEGV (-1e30f)

// ---------------- scratch (no allocations allowed) ----------------
__device__ float g_rp[256 * 6 * 4 * 512];    // roipool stage-1 partials
__device__ float g_pooled[256 * 2048];
__device__ float g_part1[16 * 256 * 200];    // FC1 split-K partials

__device__ __forceinline__ float2 fmax2(float2 a, float2 b) {
    return make_float2(fmaxf(a.x, b.x), fmaxf(a.y, b.y));
}

// packed f32x2 helpers (FFMA2 path — only reachable via PTX)
__device__ __forceinline__ unsigned long long dup2(float b) {
    unsigned long long r;
    asm("mov.b64 %0, {%1, %1};" : "=l"(r) : "f"(b));
    return r;
}
__device__ __forceinline__ void ffma2(unsigned long long& acc,
                                      unsigned long long a,
                                      unsigned long long b) {
    asm("fma.rn.f32x2 %0, %1, %2, %3;" : "=l"(acc) : "l"(a), "l"(b), "l"(acc));
}
__device__ __forceinline__ float2 unpack2(unsigned long long v) {
    float lo, hi;
    asm("mov.b64 {%0, %1}, %2;" : "=f"(lo), "=f"(hi) : "l"(v));
    return make_float2(lo, hi);
}

// ---------------- Kernel 1a: ROI pool stage 1 (row-chunk partials) ----------
// grid = (256 proposals, 6 row-chunks of 4), block = 256 threads (float2 ch)
// All feature-map accesses are provably in-bounds (ey<=76, ex<=128; forced
// h,w=2 cases keep sy+1<=75, sx+1<=127), so no validity predicates needed.
__global__ void roipool_stage1(const float* __restrict__ fm,
                               const int* __restrict__ coords,
                               float* __restrict__ rp) {
    const int p = blockIdx.x;
    const int ci = blockIdx.y;
    const int tid = threadIdx.x;

    const int y0 = coords[p * 4 + 0];
    const int x0 = coords[p * 4 + 1];
    const int y1 = coords[p * 4 + 2];
    const int x1 = coords[p * 4 + 3];

    const int sy = min(y0 / 8, 74);
    const int sx = min(x0 / 8, 126);
    const int ey = (y1 + 7) / 8;
    const int ex = (x1 + 7) / 8;
    const int h = max(ey - sy, 2);     // <= 24
    const int w = max(ex - sx, 2);     // <= 24

    const int r0 = ci * 4;
    if (r0 >= h) return;               // inactive chunk; stage 2 skips it
    const int r1 = min(r0 + 4, h);

    const int e0r = (h + 1) / 2;       // row bin0: [0, e0r)
    const int s1r = h / 2;             // row bin1: [s1r, h)
    const int e0c = (w + 1) / 2;
    const int s1c = w / 2;

    float2 m00 = make_float2(NEGV, NEGV), m01 = m00, m10 = m00, m11 = m00;

    for (int r = r0; r < r1; r++) {
        const float* rowbase = fm + ((size_t)((sy + r) * 128 + sx)) * 512 + 2 * tid;
        float2 c0 = make_float2(NEGV, NEGV);
        float2 c1 = make_float2(NEGV, NEGV);
        #pragma unroll 6
        for (int c = 0; c < w; c++) {
            const float2 v = *reinterpret_cast<const float2*>(rowbase + (size_t)c * 512);
            if (c < e0c)  c0 = fmax2(c0, v);
            if (c >= s1c) c1 = fmax2(c1, v);
        }
        if (r < e0r)  { m00 = fmax2(m00, c0); m01 = fmax2(m01, c1); }
        if (r >= s1r) { m10 = fmax2(m10, c0); m11 = fmax2(m11, c1); }
    }

    float* outp = rp + ((size_t)(p * 6 + ci) * 4) * 512 + 2 * tid;
    *reinterpret_cast<float2*>(outp + 0 * 512) = m00;
    *reinterpret_cast<float2*>(outp + 1 * 512) = m01;
    *reinterpret_cast<float2*>(outp + 2 * 512) = m10;
    *reinterpret_cast<float2*>(outp + 3 * 512) = m11;
}

// ---------------- Kernel 1b: ROI pool stage 2 (chunk reduction) ------------
// grid = 256, block = 256 threads
__global__ void roipool_stage2(const int* __restrict__ coords,
                               const float* __restrict__ rp,
                               float* __restrict__ pooled) {
    const int p = blockIdx.x;
    const int tid = threadIdx.x;

    const int y0 = coords[p * 4 + 0];
    const int y1 = coords[p * 4 + 2];
    const int sy = min(y0 / 8, 74);
    const int ey = (y1 + 7) / 8;
    const int h = max(ey - sy, 2);
    const int nchunks = (h + 3) / 4;   // 1..6 active chunks

    const float* base = rp + ((size_t)p * 6 * 4) * 512 + 2 * tid;
    float* outp = pooled + (size_t)p * 2048 + 2 * tid;

    #pragma unroll
    for (int bin = 0; bin < 4; bin++) {
        float2 m = *reinterpret_cast<const float2*>(base + (size_t)bin * 512);
        for (int ci = 1; ci < nchunks; ci++) {
            const float2 v = *reinterpret_cast<const float2*>(
                base + ((size_t)ci * 4 + bin) * 512);
            m = fmax2(m, v);
        }
        *reinterpret_cast<float2*>(outp + (size_t)bin * 512) = m;
    }
}

// ---------------- Kernel 2: FC1 split-K partial GEMM (FFMA2) ----------------
// A = pooled [256,2048], B = W1 [2048,200]
// grid = (32 mtiles of 8 rows, 16 K-splits of 128), block = 200 threads
__global__ void fc1_partial(const float* __restrict__ A,
                            const float* __restrict__ B,
                            float* __restrict__ part) {
    __shared__ float As[128][8];
    const int mt = blockIdx.x;
    const int ks = blockIdx.y;
    const int tid = threadIdx.x;
    const int m0 = mt * 8;
    const int k0 = ks * 128;

    for (int idx = tid; idx < 8 * 128; idx += 200) {
        const int r = idx >> 7;
        const int k = idx & 127;
        As[k][r] = A[(size_t)(m0 + r) * 2048 + k0 + k];
    }
    __syncthreads();

    const int j = tid;
    unsigned long long acc01 = 0ull, acc23 = 0ull, acc45 = 0ull, acc67 = 0ull;

    const float* Bp = B + (size_t)k0 * 200 + j;
    #pragma unroll
    for (int kb = 0; kb < 128; kb += 8) {
        float b[8];
        #pragma unroll
        for (int u = 0; u < 8; u++) b[u] = Bp[(size_t)(kb + u) * 200];
        #pragma unroll
        for (int u = 0; u < 8; u++) {
            const unsigned long long bd = dup2(b[u]);
            const ulonglong2 lo = *reinterpret_cast<const ulonglong2*>(&As[kb + u][0]);
            const ulonglong2 hi = *reinterpret_cast<const ulonglong2*>(&As[kb + u][4]);
            ffma2(acc01, lo.x, bd);
            ffma2(acc23, lo.y, bd);
            ffma2(acc45, hi.x, bd);
            ffma2(acc67, hi.y, bd);
        }
    }

    float* out = part + ((size_t)ks * 256 + m0) * 200 + j;
    const float2 r01 = unpack2(acc01);
    const float2 r23 = unpack2(acc23);
    const float2 r45 = unpack2(acc45);
    const float2 r67 = unpack2(acc67);
    out[0 * 200] = r01.x;  out[1 * 200] = r01.y;
    out[2 * 200] = r23.x;  out[3 * 200] = r23.y;
    out[4 * 200] = r45.x;  out[5 * 200] = r45.y;
    out[6 * 200] = r67.x;  out[7 * 200] = r67.y;
}

// ---------------- Kernel 3: fused reduce + FC2 + heads + decode ----------------
// grid = 128 blocks (2 proposals each), block = 200 threads
__global__ void fused_tail(const float* __restrict__ part,
                           const float* __restrict__ b1,
                           const float* __restrict__ W2,
                           const float* __restrict__ b2,
                           const int* __restrict__ coords,
                           const float* __restrict__ W3,
                           const float* __restrict__ b3,
                           const float* __restrict__ W4,
                           const float* __restrict__ b4,
                           float* __restrict__ out) {
    __shared__ float2 Ap[200];        // f1 row-pair, interleaved (row0, row1)
    __shared__ float fs[2][200];      // f2 rows
    __shared__ float op[2][21][4];    // head partial sums
    __shared__ float os[2][21];       // head outputs

    const int m0 = blockIdx.x * 2;
    const int tid = threadIdx.x;
    const int j = tid;

    // ---- phase 1: split-K reduce + bias + relu -> f1 pair in smem ----
    {
        const float bj = b1[j];
        float s0 = bj, s1 = bj;
        const float* p0 = part + (size_t)m0 * 200 + j;
        #pragma unroll
        for (int ks = 0; ks < 16; ks++) {
            s0 += p0[(size_t)ks * 51200];
            s1 += p0[(size_t)ks * 51200 + 200];
        }
        Ap[j] = make_float2(fmaxf(s0, 0.0f), fmaxf(s1, 0.0f));
    }
    __syncthreads();

    // ---- phase 2: FC2 (FFMA2 over row pair, 8-wide load batches) ----
    {
        unsigned long long acc = 0ull;
        const float* Bp = W2 + j;
        #pragma unroll
        for (int kb = 0; kb < 200; kb += 8) {
            float b[8];
            #pragma unroll
            for (int u = 0; u < 8; u++) b[u] = Bp[(size_t)(kb + u) * 200];
            #pragma unroll
            for (int u = 0; u < 8; u++) {
                const unsigned long long a =
                    *reinterpret_cast<const unsigned long long*>(&Ap[kb + u]);
                ffma2(acc, a, dup2(b[u]));
            }
        }
        const float2 v = unpack2(acc);
        const float bj = b2[j];
        fs[0][j] = fmaxf(v.x + bj, 0.0f);
        fs[1][j] = fmaxf(v.y + bj, 0.0f);
    }
    __syncthreads();

    // ---- phase 3: head dot products, 4-way K-split over 168 threads ----
    if (tid < 168) {
        const int prop = tid / 84;
        const int rem = tid % 84;
        const int o = rem / 4;        // 0..20
        const int ks = rem % 4;       // 0..3
        const int kb = ks * 50;
        const float* wp = (o < 16) ? (W3 + o) : (W4 + (o - 16));
        const int stride = (o < 16) ? 16 : 5;
        float s0 = 0.f, s1 = 0.f;
        #pragma unroll 5
        for (int k = 0; k < 50; k += 2) {
            s0 = fmaf(fs[prop][kb + k],     wp[(size_t)(kb + k) * stride],     s0);
            s1 = fmaf(fs[prop][kb + k + 1], wp[(size_t)(kb + k + 1) * stride], s1);
        }
        op[prop][o][ks] = s0 + s1;
    }
    __syncthreads();

    if (tid < 42) {
        const int prop = tid / 21;
        const int o = tid % 21;
        const float bias = (o < 16) ? b3[o] : b4[o - 16];
        os[prop][o] = bias + (op[prop][o][0] + op[prop][o][1]) +
                             (op[prop][o][2] + op[prop][o][3]);
    }
    __syncthreads();

    // ---- phase 4: softmax / argmax / box decode for the 2 proposals ----
    if (tid < 2) {
        const int p = m0 + tid;
        const float l0 = os[tid][16], l1 = os[tid][17], l2 = os[tid][18],
                    l3 = os[tid][19], l4 = os[tid][20];
        int cls = 0;
        float best = l0;
        if (l1 > best) { best = l1; cls = 1; }
        if (l2 > best) { best = l2; cls = 2; }
        if (l3 > best) { best = l3; cls = 3; }
        if (l4 > best) { best = l4; cls = 4; }
        const float mx = best;
        const float e0 = expf(l0 - mx), e1 = expf(l1 - mx), e2 = expf(l2 - mx),
                    e3 = expf(l3 - mx), e4 = expf(l4 - mx);
        const float sum = e0 + e1 + e2 + e3 + e4;
        const float score = fmaxf(fmaxf(e1, e2), fmaxf(e3, e4)) / sum;

        const int jj = max(cls - 1, 0);
        const float r0 = os[tid][jj * 4 + 0];
        const float r1 = os[tid][jj * 4 + 1];
        const float r2 = os[tid][jj * 4 + 2];
        const float r3 = os[tid][jj * 4 + 3];

        const float y0 = (float)coords[p * 4 + 0];
        const float x0 = (float)coords[p * 4 + 1];
        const float y1 = (float)coords[p * 4 + 2];
        const float x1 = (float)coords[p * 4 + 3];
        const float ph = y1 - y0;
        const float pw = x1 - x0;
        const float py = y0 + 0.5f * ph;
        const float px = x0 + 0.5f * pw;

        out[p * 4 + 0] = fmaf(ph, r0, py);
        out[p * 4 + 1] = fmaf(pw, r1, px);
        out[p * 4 + 2] = ph * fminf(fmaxf(expf(r2), 0.001f), 20.0f);
        out[p * 4 + 3] = pw * fminf(fmaxf(expf(r3), 0.001f), 20.0f);
        out[1024 + p] = score;
        out[1280 + p] = (cls != 0) ? 1.0f : 0.0f;
    }
}

// ---------------- launch ----------------
extern "C" void kernel_launch(void* const* d_in, const int* in_sizes, int n_in,
                              void* d_out, int out_size) {
    const float* fm     = (const float*)d_in[0];
    const int*   coords = (const int*)d_in[1];
    const float* W1 = (const float*)d_in[2];
    const float* b1 = (const float*)d_in[3];
    const float* W2 = (const float*)d_in[4];
    const float* b2 = (const float*)d_in[5];
    const float* W3 = (const float*)d_in[6];
    const float* b3 = (const float*)d_in[7];
    const float* W4 = (const float*)d_in[8];
    const float* b4 = (const float*)d_in[9];
    float* out = (float*)d_out;

    float *rp = nullptr, *pooled = nullptr, *part1 = nullptr;
    cudaGetSymbolAddress((void**)&rp, g_rp);
    cudaGetSymbolAddress((void**)&pooled, g_pooled);
    cudaGetSymbolAddress((void**)&part1, g_part1);

    roipool_stage1<<<dim3(256, 6), 256>>>(fm, coords, rp);
    roipool_stage2<<<256, 256>>>(coords, rp, pooled);
    fc1_partial<<<dim3(32, 16), 200>>>(pooled, W1, part1);
    fused_tail<<<128, 200>>>(part1, b1, W2, b2, coords, W3, b3, W4, b4, out);
}